// round 13
// baseline (speedup 1.0000x reference)
#include <cuda_runtime.h>
#include <cuda_bf16.h>

// Q_Model_43782896615432 — analytic collapse of the 6-qubit circuit.
//
// Math: after RX(theta_w) on |0>, qubits are product-Bernoulli with
// E[(-1)^x] = cos(theta); the CNOT chain (0,1),(1,2),(2,0),(3,4),(4,5),(5,3)
// is a basis permutation whose Z-expectations are XOR pushforwards:
//   Z0=c1*c2, Z1=c0*c1, Z2=c0*c1*c2, Z3=c4*c5, Z4=c3*c4, Z5=c3*c4*c5
// theta[0:3] = sen @ W_sen^T + b_sen, theta[3:6] = sa @ W_sar^T + b_sar.
// sar = Z[3:6] @ W_resar^T + b_resar ; sen_out = Z[0:3] @ W_resen^T + b_resen.
//
// R13 = R5 (confirmed optimum over 12 structural perturbations):
// TPB=64, 2 samples/thread (4096 warps), weights staged to smem as 11
// (w0,w1,w2,b) float4 rows by 44 threads, input LDG.64s hoisted above the
// barrier, fully vectorized output stores. The remaining runtime is the
// launch-ramp floor (T_ovh ~5000 cyc) + per-CTA L2-latency critical path +
// cross-CTA L1tex-queue spread, none of which further config changes moved.

#define BQ 262144
#define TPB 64

__global__ __launch_bounds__(TPB)
void q_model_kernel(const float* __restrict__ sa,
                    const float* __restrict__ sen,
                    const float* __restrict__ W_sar,  const float* __restrict__ b_sar,
                    const float* __restrict__ W_sen,  const float* __restrict__ b_sen,
                    const float* __restrict__ W_resar, const float* __restrict__ b_resar,
                    const float* __restrict__ W_resen, const float* __restrict__ b_resen,
                    float* __restrict__ out)
{
    const int t = threadIdx.x;
    const int g = blockIdx.x * TPB + t;          // 0 .. 131071, exact (2 samples each)

    // ---- issue input loads FIRST: 6x LDG.64, overlap with weight staging ----
    const float2* sen2 = reinterpret_cast<const float2*>(sen) + 3 * g;
    const float2* sa2  = reinterpret_cast<const float2*>(sa)  + 3 * g;
    const float2 E0 = sen2[0], E1 = sen2[1], E2 = sen2[2];
    const float2 A0 = sa2[0],  A1 = sa2[1],  A2 = sa2[2];

    // ---- stage params into smem: rows of (w0, w1, w2, bias) ----
    // rows 0-2: W_sen/b_sen | 3-5: W_sar/b_sar | 6-7: W_resar/b_resar | 8-10: W_resen/b_resen
    __shared__ float4 P[11];
    if (t < 44) {
        const int row = t >> 2;
        const int c   = t & 3;
        float v;
        if (row < 3)      v = (c < 3) ? W_sen[row * 3 + c]         : b_sen[row];
        else if (row < 6) v = (c < 3) ? W_sar[(row - 3) * 3 + c]   : b_sar[row - 3];
        else if (row < 8) v = (c < 3) ? W_resar[(row - 6) * 3 + c] : b_resar[row - 6];
        else              v = (c < 3) ? W_resen[(row - 8) * 3 + c] : b_resen[row - 8];
        reinterpret_cast<float*>(P)[t] = v;
    }
    __syncthreads();

    const float ein[6] = {E0.x, E0.y, E1.x, E1.y, E2.x, E2.y};
    const float ain[6] = {A0.x, A0.y, A1.x, A1.y, A2.x, A2.y};

    // ---- param rows (broadcast LDS.128, conflict-free) ----
    const float4 r0 = P[0], r1 = P[1], r2 = P[2];   // theta 0-2 (sen branch)
    const float4 r3 = P[3], r4 = P[4], r5 = P[5];   // theta 3-5 (sa branch)
    const float4 q0 = P[6], q1 = P[7];              // sar output rows
    const float4 u0 = P[8], u1 = P[9], u2 = P[10];  // sen output rows

    float sarv[4];
    float senv[6];

#pragma unroll
    for (int s = 0; s < 2; s++) {
        const float e0 = ein[3 * s + 0], e1 = ein[3 * s + 1], e2 = ein[3 * s + 2];
        const float a0 = ain[3 * s + 0], a1 = ain[3 * s + 1], a2 = ain[3 * s + 2];

        const float t0 = fmaf(r0.x, e0, fmaf(r0.y, e1, fmaf(r0.z, e2, r0.w)));
        const float t1 = fmaf(r1.x, e0, fmaf(r1.y, e1, fmaf(r1.z, e2, r1.w)));
        const float t2 = fmaf(r2.x, e0, fmaf(r2.y, e1, fmaf(r2.z, e2, r2.w)));
        const float t3 = fmaf(r3.x, a0, fmaf(r3.y, a1, fmaf(r3.z, a2, r3.w)));
        const float t4 = fmaf(r4.x, a0, fmaf(r4.y, a1, fmaf(r4.z, a2, r4.w)));
        const float t5 = fmaf(r5.x, a0, fmaf(r5.y, a1, fmaf(r5.z, a2, r5.w)));

        const float c0 = __cosf(t0), c1 = __cosf(t1), c2 = __cosf(t2);
        const float c3 = __cosf(t3), c4 = __cosf(t4), c5 = __cosf(t5);

        const float Z0 = c1 * c2;
        const float Z1 = c0 * c1;
        const float Z2 = Z1 * c2;
        const float Z3 = c4 * c5;
        const float Z4 = c3 * c4;
        const float Z5 = Z4 * c5;

        sarv[2 * s + 0] = fmaf(q0.x, Z3, fmaf(q0.y, Z4, fmaf(q0.z, Z5, q0.w)));
        sarv[2 * s + 1] = fmaf(q1.x, Z3, fmaf(q1.y, Z4, fmaf(q1.z, Z5, q1.w)));

        senv[3 * s + 0] = fmaf(u0.x, Z0, fmaf(u0.y, Z1, fmaf(u0.z, Z2, u0.w)));
        senv[3 * s + 1] = fmaf(u1.x, Z0, fmaf(u1.y, Z1, fmaf(u1.z, Z2, u1.w)));
        senv[3 * s + 2] = fmaf(u2.x, Z0, fmaf(u2.y, Z1, fmaf(u2.z, Z2, u2.w)));
    }

    // ---- outputs: sar block [0, 2B) as STG.128; sen block [2B, 5B) as 3x STG.64 ----
    reinterpret_cast<float4*>(out)[g] = make_float4(sarv[0], sarv[1], sarv[2], sarv[3]);

    float2* so = reinterpret_cast<float2*>(out + 2 * BQ) + 3 * g;
    so[0] = make_float2(senv[0], senv[1]);
    so[1] = make_float2(senv[2], senv[3]);
    so[2] = make_float2(senv[4], senv[5]);
}

extern "C" void kernel_launch(void* const* d_in, const int* in_sizes, int n_in,
                              void* d_out, int out_size) {
    const float* sa      = (const float*)d_in[0];
    const float* sen     = (const float*)d_in[1];
    const float* W_sar   = (const float*)d_in[2];
    const float* b_sar   = (const float*)d_in[3];
    const float* W_sen   = (const float*)d_in[4];
    const float* b_sen   = (const float*)d_in[5];
    const float* W_resar = (const float*)d_in[6];
    const float* b_resar = (const float*)d_in[7];
    const float* W_resen = (const float*)d_in[8];
    const float* b_resen = (const float*)d_in[9];
    float* out = (float*)d_out;

    q_model_kernel<<<(BQ / 2) / TPB, TPB>>>(sa, sen, W_sar, b_sar, W_sen, b_sen,
                                            W_resar, b_resar, W_resen, b_resen, out);
}

// round 14
// speedup vs baseline: 1.0829x; 1.0829x over previous
#include <cuda_runtime.h>
#include <cuda_bf16.h>

// Q_Model_43782896615432 — analytic collapse of the 6-qubit circuit. FINAL.
//
// Math: after RX(theta_w) on |0>, qubits are product-Bernoulli with
// E[(-1)^x] = cos(theta); the CNOT chain (0,1),(1,2),(2,0),(3,4),(4,5),(5,3)
// is a basis permutation whose Z-expectations are XOR pushforwards:
//   Z0=c1*c2, Z1=c0*c1, Z2=c0*c1*c2, Z3=c4*c5, Z4=c3*c4, Z5=c3*c4*c5
// theta[0:3] = sen @ W_sen^T + b_sen, theta[3:6] = sa @ W_sar^T + b_sar.
// sar = Z[3:6] @ W_resar^T + b_resar ; sen_out = Z[0:3] @ W_resen^T + b_resen.
//
// Confirmed optimum over 13 structural perturbations (warp count, block
// size, weight-staging strategy, load ordering, register cap): TPB=64,
// 2 samples/thread (4096 warps), weights staged to smem as 11 (w0,w1,w2,b)
// float4 rows by 44 threads, input LDG.64s hoisted above the barrier, fully
// vectorized stores. Remaining runtime = launch-ramp floor + per-CTA
// L2-latency critical path + cross-CTA L1tex-queue spread.

#define BQ 262144
#define TPB 64

__global__ __launch_bounds__(TPB)
void q_model_kernel(const float* __restrict__ sa,
                    const float* __restrict__ sen,
                    const float* __restrict__ W_sar,  const float* __restrict__ b_sar,
                    const float* __restrict__ W_sen,  const float* __restrict__ b_sen,
                    const float* __restrict__ W_resar, const float* __restrict__ b_resar,
                    const float* __restrict__ W_resen, const float* __restrict__ b_resen,
                    float* __restrict__ out)
{
    const int t = threadIdx.x;
    const int g = blockIdx.x * TPB + t;          // 0 .. 131071, exact (2 samples each)

    // ---- issue input loads FIRST: 6x LDG.64, overlap with weight staging ----
    const float2* sen2 = reinterpret_cast<const float2*>(sen) + 3 * g;
    const float2* sa2  = reinterpret_cast<const float2*>(sa)  + 3 * g;
    const float2 E0 = sen2[0], E1 = sen2[1], E2 = sen2[2];
    const float2 A0 = sa2[0],  A1 = sa2[1],  A2 = sa2[2];

    // ---- stage params into smem: rows of (w0, w1, w2, bias) ----
    // rows 0-2: W_sen/b_sen | 3-5: W_sar/b_sar | 6-7: W_resar/b_resar | 8-10: W_resen/b_resen
    __shared__ float4 P[11];
    if (t < 44) {
        const int row = t >> 2;
        const int c   = t & 3;
        float v;
        if (row < 3)      v = (c < 3) ? W_sen[row * 3 + c]         : b_sen[row];
        else if (row < 6) v = (c < 3) ? W_sar[(row - 3) * 3 + c]   : b_sar[row - 3];
        else if (row < 8) v = (c < 3) ? W_resar[(row - 6) * 3 + c] : b_resar[row - 6];
        else              v = (c < 3) ? W_resen[(row - 8) * 3 + c] : b_resen[row - 8];
        reinterpret_cast<float*>(P)[t] = v;
    }
    __syncthreads();

    const float ein[6] = {E0.x, E0.y, E1.x, E1.y, E2.x, E2.y};
    const float ain[6] = {A0.x, A0.y, A1.x, A1.y, A2.x, A2.y};

    // ---- param rows (broadcast LDS.128, conflict-free) ----
    const float4 r0 = P[0], r1 = P[1], r2 = P[2];   // theta 0-2 (sen branch)
    const float4 r3 = P[3], r4 = P[4], r5 = P[5];   // theta 3-5 (sa branch)
    const float4 q0 = P[6], q1 = P[7];              // sar output rows
    const float4 u0 = P[8], u1 = P[9], u2 = P[10];  // sen output rows

    float sarv[4];
    float senv[6];

#pragma unroll
    for (int s = 0; s < 2; s++) {
        const float e0 = ein[3 * s + 0], e1 = ein[3 * s + 1], e2 = ein[3 * s + 2];
        const float a0 = ain[3 * s + 0], a1 = ain[3 * s + 1], a2 = ain[3 * s + 2];

        const float t0 = fmaf(r0.x, e0, fmaf(r0.y, e1, fmaf(r0.z, e2, r0.w)));
        const float t1 = fmaf(r1.x, e0, fmaf(r1.y, e1, fmaf(r1.z, e2, r1.w)));
        const float t2 = fmaf(r2.x, e0, fmaf(r2.y, e1, fmaf(r2.z, e2, r2.w)));
        const float t3 = fmaf(r3.x, a0, fmaf(r3.y, a1, fmaf(r3.z, a2, r3.w)));
        const float t4 = fmaf(r4.x, a0, fmaf(r4.y, a1, fmaf(r4.z, a2, r4.w)));
        const float t5 = fmaf(r5.x, a0, fmaf(r5.y, a1, fmaf(r5.z, a2, r5.w)));

        const float c0 = __cosf(t0), c1 = __cosf(t1), c2 = __cosf(t2);
        const float c3 = __cosf(t3), c4 = __cosf(t4), c5 = __cosf(t5);

        const float Z0 = c1 * c2;
        const float Z1 = c0 * c1;
        const float Z2 = Z1 * c2;
        const float Z3 = c4 * c5;
        const float Z4 = c3 * c4;
        const float Z5 = Z4 * c5;

        sarv[2 * s + 0] = fmaf(q0.x, Z3, fmaf(q0.y, Z4, fmaf(q0.z, Z5, q0.w)));
        sarv[2 * s + 1] = fmaf(q1.x, Z3, fmaf(q1.y, Z4, fmaf(q1.z, Z5, q1.w)));

        senv[3 * s + 0] = fmaf(u0.x, Z0, fmaf(u0.y, Z1, fmaf(u0.z, Z2, u0.w)));
        senv[3 * s + 1] = fmaf(u1.x, Z0, fmaf(u1.y, Z1, fmaf(u1.z, Z2, u1.w)));
        senv[3 * s + 2] = fmaf(u2.x, Z0, fmaf(u2.y, Z1, fmaf(u2.z, Z2, u2.w)));
    }

    // ---- outputs: sar block [0, 2B) as STG.128; sen block [2B, 5B) as 3x STG.64 ----
    reinterpret_cast<float4*>(out)[g] = make_float4(sarv[0], sarv[1], sarv[2], sarv[3]);

    float2* so = reinterpret_cast<float2*>(out + 2 * BQ) + 3 * g;
    so[0] = make_float2(senv[0], senv[1]);
    so[1] = make_float2(senv[2], senv[3]);
    so[2] = make_float2(senv[4], senv[5]);
}

extern "C" void kernel_launch(void* const* d_in, const int* in_sizes, int n_in,
                              void* d_out, int out_size) {
    const float* sa      = (const float*)d_in[0];
    const float* sen     = (const float*)d_in[1];
    const float* W_sar   = (const float*)d_in[2];
    const float* b_sar   = (const float*)d_in[3];
    const float* W_sen   = (const float*)d_in[4];
    const float* b_sen   = (const float*)d_in[5];
    const float* W_resar = (const float*)d_in[6];
    const float* b_resar = (const float*)d_in[7];
    const float* W_resen = (const float*)d_in[8];
    const float* b_resen = (const float*)d_in[9];
    float* out = (float*)d_out;

    q_model_kernel<<<(BQ / 2) / TPB, TPB>>>(sa, sen, W_sar, b_sar, W_sen, b_sen,
                                            W_resar, b_resar, W_resen, b_resen, out);
}